// round 1
// baseline (speedup 1.0000x reference)
#include <cuda_runtime.h>

#define SEQ    2048
#define BATCH  2
#define DMODEL 1024
#define NH     16
#define DKH    64
#define TOK    (SEQ * BATCH)   // 4096

// Scratch (alloc-free rule: __device__ globals)
__device__ float g_q[NH * BATCH * SEQ * DKH];     // [h][b][s][dk]
__device__ float g_k[NH * BATCH * SEQ * DKH];
__device__ float g_v[NH * BATCH * SEQ * DKH];
__device__ float g_attn[TOK * DMODEL];            // [s*B+b][dmodel]

// ---------------------------------------------------------------------------
// GEMM: C[t][n] = sum_k A[t][k] * W[n][k] + bias[n]
// A: [4096,1024] row-major, W: [1024,1024] row-major (used transposed)
// qkv_mode = 1: scatter output to [h][b][s][dk]; 0: plain [t][n]
// Tile 64x64, BK=16, 256 threads, 4x4 microtile.
// ---------------------------------------------------------------------------
__global__ __launch_bounds__(256)
void gemm_bias_kernel(const float* __restrict__ A, const float* __restrict__ W,
                      const float* __restrict__ bias, float* __restrict__ out,
                      int qkv_mode)
{
    __shared__ float As[16][68];   // [k][m], pad 68 keeps float4 alignment
    __shared__ float Ws[16][68];   // [k][n]

    const int tid = threadIdx.x;
    const int tx = tid & 15;       // n quad
    const int ty = tid >> 4;       // m quad
    const int m0 = blockIdx.y * 64;
    const int n0 = blockIdx.x * 64;

    const int lr = tid >> 2;       // 0..63 row for loads
    const int lq = tid & 3;        // 0..3 k-quad for loads

    const float* Ap = A + (size_t)(m0 + lr) * DMODEL + lq * 4;
    const float* Wp = W + (size_t)(n0 + lr) * DMODEL + lq * 4;

    float acc[4][4] = {};

    for (int kt = 0; kt < DMODEL; kt += 16) {
        float4 a = *(const float4*)(Ap + kt);
        float4 w = *(const float4*)(Wp + kt);
        As[lq * 4 + 0][lr] = a.x; As[lq * 4 + 1][lr] = a.y;
        As[lq * 4 + 2][lr] = a.z; As[lq * 4 + 3][lr] = a.w;
        Ws[lq * 4 + 0][lr] = w.x; Ws[lq * 4 + 1][lr] = w.y;
        Ws[lq * 4 + 2][lr] = w.z; Ws[lq * 4 + 3][lr] = w.w;
        __syncthreads();

#pragma unroll
        for (int kk = 0; kk < 16; kk++) {
            float4 a4 = *(const float4*)&As[kk][ty * 4];
            float4 b4 = *(const float4*)&Ws[kk][tx * 4];
            float av[4] = {a4.x, a4.y, a4.z, a4.w};
            float bv[4] = {b4.x, b4.y, b4.z, b4.w};
#pragma unroll
            for (int i = 0; i < 4; i++)
#pragma unroll
                for (int j = 0; j < 4; j++)
                    acc[i][j] = fmaf(av[i], bv[j], acc[i][j]);
        }
        __syncthreads();
    }

    float4 bb4 = *(const float4*)(bias + n0 + tx * 4);
    float bv[4] = {bb4.x, bb4.y, bb4.z, bb4.w};

    if (qkv_mode) {
        const int h = n0 >> 6;  // BN == DKH == 64 -> one head per block column
#pragma unroll
        for (int i = 0; i < 4; i++) {
            int t = m0 + ty * 4 + i;
            int s = t >> 1;
            int b = t & 1;
            float4 o;
            o.x = acc[i][0] + bv[0];
            o.y = acc[i][1] + bv[1];
            o.z = acc[i][2] + bv[2];
            o.w = acc[i][3] + bv[3];
            *(float4*)(out + ((size_t)(h * BATCH + b) * SEQ + s) * DKH + tx * 4) = o;
        }
    } else {
#pragma unroll
        for (int i = 0; i < 4; i++) {
            int t = m0 + ty * 4 + i;
            float4 o;
            o.x = acc[i][0] + bv[0];
            o.y = acc[i][1] + bv[1];
            o.z = acc[i][2] + bv[2];
            o.w = acc[i][3] + bv[3];
            *(float4*)(out + (size_t)t * DMODEL + n0 + tx * 4) = o;
        }
    }
}

// ---------------------------------------------------------------------------
// Flash attention, fp32. One block = one (h,b) pair x one 64-row Q tile.
// Br = Bc = 64, dk = 64. Online softmax. 256 threads, 4x4 microtiles.
// Smem: Qs/Ks d-major (transposed) for float4 GEMM loads; Vs row-major.
// ---------------------------------------------------------------------------
#define FL_STRIDE 68
#define FLASH_SMEM_FLOATS (4 * 64 * FL_STRIDE + 3 * 64)
#define FLASH_SMEM_BYTES  (FLASH_SMEM_FLOATS * 4)

__global__ __launch_bounds__(256)
void flash_kernel(const float* __restrict__ Q, const float* __restrict__ K,
                  const float* __restrict__ V, float* __restrict__ O)
{
    extern __shared__ float sm[];
    float* Qs   = sm;                       // [d][r]  64 x FL_STRIDE
    float* Ks   = Qs + 64 * FL_STRIDE;      // [d][c]
    float* Vs   = Ks + 64 * FL_STRIDE;      // [c][d]
    float* Ss   = Vs + 64 * FL_STRIDE;      // [r][c]
    float* mrow = Ss + 64 * FL_STRIDE;      // [64]
    float* lrow = mrow + 64;                // [64]
    float* arow = lrow + 64;                // [64]

    const int qt = blockIdx.x;
    const int hb = blockIdx.y;              // h * BATCH + b
    const int tid = threadIdx.x;
    const int tx = tid & 15;
    const int ty = tid >> 4;

    const float* Qb = Q + (size_t)hb * SEQ * DKH + (size_t)qt * 64 * DKH;
    const float* Kb = K + (size_t)hb * SEQ * DKH;
    const float* Vb = V + (size_t)hb * SEQ * DKH;

    // Load Q tile, transposed + pre-scaled by 1/sqrt(dk)=0.125
#pragma unroll
    for (int i = 0; i < 4; i++) {
        int lin = tid + i * 256;            // float4 index 0..1023
        int r = lin >> 4;
        int dq = lin & 15;
        float4 v = *(const float4*)(Qb + r * DKH + dq * 4);
        Qs[(dq * 4 + 0) * FL_STRIDE + r] = v.x * 0.125f;
        Qs[(dq * 4 + 1) * FL_STRIDE + r] = v.y * 0.125f;
        Qs[(dq * 4 + 2) * FL_STRIDE + r] = v.z * 0.125f;
        Qs[(dq * 4 + 3) * FL_STRIDE + r] = v.w * 0.125f;
    }
    if (tid < 64) { mrow[tid] = -1e30f; lrow[tid] = 0.0f; }

    float o[4][4] = {};

    __syncthreads();

    for (int kt = 0; kt < SEQ / 64; kt++) {
        const float* Kt = Kb + (size_t)kt * 64 * DKH;
        const float* Vt = Vb + (size_t)kt * 64 * DKH;
#pragma unroll
        for (int i = 0; i < 4; i++) {
            int lin = tid + i * 256;
            int r = lin >> 4;
            int dq = lin & 15;
            float4 kv = *(const float4*)(Kt + r * DKH + dq * 4);
            Ks[(dq * 4 + 0) * FL_STRIDE + r] = kv.x;
            Ks[(dq * 4 + 1) * FL_STRIDE + r] = kv.y;
            Ks[(dq * 4 + 2) * FL_STRIDE + r] = kv.z;
            Ks[(dq * 4 + 3) * FL_STRIDE + r] = kv.w;
            float4 vv = *(const float4*)(Vt + r * DKH + dq * 4);
            *(float4*)&Vs[r * FL_STRIDE + dq * 4] = vv;
        }
        __syncthreads();

        // S = Q @ K^T (already scaled)
        float s[4][4] = {};
#pragma unroll 8
        for (int d = 0; d < 64; d++) {
            float4 a4 = *(const float4*)&Qs[d * FL_STRIDE + ty * 4];
            float4 b4 = *(const float4*)&Ks[d * FL_STRIDE + tx * 4];
            float av[4] = {a4.x, a4.y, a4.z, a4.w};
            float bvv[4] = {b4.x, b4.y, b4.z, b4.w};
#pragma unroll
            for (int i = 0; i < 4; i++)
#pragma unroll
                for (int j = 0; j < 4; j++)
                    s[i][j] = fmaf(av[i], bvv[j], s[i][j]);
        }
#pragma unroll
        for (int i = 0; i < 4; i++)
#pragma unroll
            for (int j = 0; j < 4; j++)
                Ss[(ty * 4 + i) * FL_STRIDE + tx * 4 + j] = s[i][j];
        __syncthreads();

        // Online softmax per row (64 row-threads)
        if (tid < 64) {
            float* row = &Ss[tid * FL_STRIDE];
            float mx = mrow[tid];
#pragma unroll 8
            for (int c = 0; c < 64; c++) mx = fmaxf(mx, row[c]);
            float al = __expf(mrow[tid] - mx);
            float sum = 0.0f;
#pragma unroll 8
            for (int c = 0; c < 64; c++) {
                float p = __expf(row[c] - mx);
                row[c] = p;
                sum += p;
            }
            lrow[tid] = lrow[tid] * al + sum;
            mrow[tid] = mx;
            arow[tid] = al;
        }
        __syncthreads();

        // Rescale O and accumulate P @ V
        float al[4];
#pragma unroll
        for (int i = 0; i < 4; i++) al[i] = arow[ty * 4 + i];
#pragma unroll
        for (int i = 0; i < 4; i++)
#pragma unroll
            for (int j = 0; j < 4; j++)
                o[i][j] *= al[i];

#pragma unroll 8
        for (int c = 0; c < 64; c++) {
            float pv[4];
#pragma unroll
            for (int i = 0; i < 4; i++) pv[i] = Ss[(ty * 4 + i) * FL_STRIDE + c];
            float4 v4 = *(const float4*)&Vs[c * FL_STRIDE + tx * 4];
            float vv[4] = {v4.x, v4.y, v4.z, v4.w};
#pragma unroll
            for (int i = 0; i < 4; i++)
#pragma unroll
                for (int j = 0; j < 4; j++)
                    o[i][j] = fmaf(pv[i], vv[j], o[i][j]);
        }
        __syncthreads();
    }

    // Epilogue: O /= l, write to [s][b][h*64+dk]
    const int h = hb / BATCH;
    const int b = hb % BATCH;
#pragma unroll
    for (int i = 0; i < 4; i++) {
        int r = ty * 4 + i;
        float inv = 1.0f / lrow[r];
        int s_idx = qt * 64 + r;
        int t = s_idx * BATCH + b;
        float4 ov;
        ov.x = o[i][0] * inv;
        ov.y = o[i][1] * inv;
        ov.z = o[i][2] * inv;
        ov.w = o[i][3] * inv;
        *(float4*)(O + (size_t)t * DMODEL + h * DKH + tx * 4) = ov;
    }
}

// ---------------------------------------------------------------------------
extern "C" void kernel_launch(void* const* d_in, const int* in_sizes, int n_in,
                              void* d_out, int out_size)
{
    const float* query = (const float*)d_in[0];
    const float* key_  = (const float*)d_in[1];
    const float* value = (const float*)d_in[2];
    const float* Wq = (const float*)d_in[3];
    const float* bq = (const float*)d_in[4];
    const float* Wk = (const float*)d_in[5];
    const float* bk = (const float*)d_in[6];
    const float* Wv = (const float*)d_in[7];
    const float* bv = (const float*)d_in[8];
    const float* Wo = (const float*)d_in[9];
    const float* bo = (const float*)d_in[10];

    float *qp, *kp, *vp, *ap;
    cudaGetSymbolAddress((void**)&qp, g_q);
    cudaGetSymbolAddress((void**)&kp, g_k);
    cudaGetSymbolAddress((void**)&vp, g_v);
    cudaGetSymbolAddress((void**)&ap, g_attn);

    cudaFuncSetAttribute(flash_kernel,
                         cudaFuncAttributeMaxDynamicSharedMemorySize,
                         FLASH_SMEM_BYTES);

    dim3 ggrid(DMODEL / 64, TOK / 64);   // (16, 64)

    gemm_bias_kernel<<<ggrid, 256>>>(query, Wq, bq, qp, 1);
    gemm_bias_kernel<<<ggrid, 256>>>(key_, Wk, bk, kp, 1);
    gemm_bias_kernel<<<ggrid, 256>>>(value, Wv, bv, vp, 1);

    flash_kernel<<<dim3(SEQ / 64, NH * BATCH), 256, FLASH_SMEM_BYTES>>>(qp, kp, vp, ap);

    gemm_bias_kernel<<<ggrid, 256>>>(ap, Wo, bo, (float*)d_out, 0);
}

// round 3
// speedup vs baseline: 1.4754x; 1.4754x over previous
#include <cuda_runtime.h>
#include <cuda_bf16.h>
#include <cstdint>

#define SEQ    2048
#define BATCH  2
#define DMODEL 1024
#define NH     16
#define DKH    64
#define TOK    (SEQ * BATCH)   // 4096

// ---------------------------------------------------------------------------
// Scratch (__device__ globals: the sanctioned alloc-free workaround)
// ---------------------------------------------------------------------------
__device__ float g_q[NH * BATCH * SEQ * DKH];     // [h][b][s][dk]
__device__ float g_k[NH * BATCH * SEQ * DKH];
__device__ float g_v[NH * BATCH * SEQ * DKH];
__device__ float g_attn[TOK * DMODEL];            // [t][dmodel], t = s*B+b

__device__ __nv_bfloat16 g_Ah[TOK * DMODEL];      // split activation hi/lo
__device__ __nv_bfloat16 g_Al[TOK * DMODEL];
__device__ __nv_bfloat16 g_Wh[DMODEL * DMODEL];   // split weight hi/lo
__device__ __nv_bfloat16 g_Wl[DMODEL * DMODEL];

// ---------------------------------------------------------------------------
// Helpers (sm_80-era PTX only: no tcgen05 — blocked by compute_103 target)
// ---------------------------------------------------------------------------
__device__ __forceinline__ uint32_t smem_u32(const void* p) {
    uint32_t a;
    asm("{ .reg .u64 t; cvta.to.shared.u64 t, %1; cvt.u32.u64 %0, t; }"
        : "=r"(a) : "l"(p));
    return a;
}

#define CPA(dst, src) \
    asm volatile("cp.async.cg.shared.global [%0], [%1], 16;" :: "r"(dst), "l"(src))

#define CPA_COMMIT() asm volatile("cp.async.commit_group;" ::: "memory")
#define CPA_WAIT0()  asm volatile("cp.async.wait_group 0;" ::: "memory")
#define CPA_WAIT1()  asm volatile("cp.async.wait_group 1;" ::: "memory")

#define LDSM4(r, addr) \
    asm volatile("ldmatrix.sync.aligned.m8n8.x4.shared.b16 {%0,%1,%2,%3}, [%4];" \
        : "=r"((r)[0]), "=r"((r)[1]), "=r"((r)[2]), "=r"((r)[3]) : "r"(addr))

#define MMA16816(c, a, b0, b1) \
    asm volatile("mma.sync.aligned.m16n8k16.row.col.f32.bf16.bf16.f32 " \
        "{%0,%1,%2,%3}, {%4,%5,%6,%7}, {%8,%9}, {%0,%1,%2,%3};" \
        : "+f"((c)[0]), "+f"((c)[1]), "+f"((c)[2]), "+f"((c)[3]) \
        : "r"((a)[0]), "r"((a)[1]), "r"((a)[2]), "r"((a)[3]), "r"(b0), "r"(b1))

// ---------------------------------------------------------------------------
// fp32 -> bf16 hi/lo split (pre-pass)
// ---------------------------------------------------------------------------
__global__ __launch_bounds__(256)
void cvt_split_kernel(const float* __restrict__ x, __nv_bfloat16* __restrict__ hi,
                      __nv_bfloat16* __restrict__ lo, int n4)
{
    int i = blockIdx.x * blockDim.x + threadIdx.x;
    if (i >= n4) return;
    float4 v = ((const float4*)x)[i];
    float vv[4] = {v.x, v.y, v.z, v.w};
    __nv_bfloat16 h[4], l[4];
#pragma unroll
    for (int j = 0; j < 4; j++) {
        h[j] = __float2bfloat16(vv[j]);
        l[j] = __float2bfloat16(vv[j] - __bfloat162float(h[j]));
    }
    union { __nv_bfloat16 b[4]; uint2 u; } ph, pl;
#pragma unroll
    for (int j = 0; j < 4; j++) { ph.b[j] = h[j]; pl.b[j] = l[j]; }
    ((uint2*)hi)[i] = ph.u;
    ((uint2*)lo)[i] = pl.u;
}

// ---------------------------------------------------------------------------
// bf16x3 tensor-core GEMM via mma.sync:
//   out[t][n] = sum_k A[t][k]*W[n][k] + bias[n]
// CTA tile 128x128, K-chunk 64, 2-stage cp.async pipeline.
// 8 warps, each 32(M) x 64(N). SW128-swizzled smem, conflict-free ldmatrix.
// qkv_mode=1: scatter to [h][b][s][dk]; 0: plain [t][n]
// ---------------------------------------------------------------------------
#define BM 128
#define BN 128
#define BK 64
#define A_SZ (BM * BK * 2)                 // 16384 bytes per half-tensor
#define STAGE_BYTES (4 * A_SZ)             // Ah, Al, Bh, Bl = 65536
#define GEMM_SMEM (2 * STAGE_BYTES + 1024)
#define NCHUNK (DMODEL / BK)               // 16

__global__ __launch_bounds__(256, 1)
void gemm_mma_kernel(const __nv_bfloat16* __restrict__ Ah, const __nv_bfloat16* __restrict__ Al,
                     const __nv_bfloat16* __restrict__ Wh, const __nv_bfloat16* __restrict__ Wl,
                     const float* __restrict__ bias, float* __restrict__ out, int qkv_mode)
{
    extern __shared__ char dsm_raw[];
    char* dsm = (char*)(((uintptr_t)dsm_raw + 1023) & ~(uintptr_t)1023);
    const uint32_t sm0 = smem_u32(dsm);

    const int tid  = threadIdx.x;
    const int wid  = tid >> 5;
    const int lane = tid & 31;
    const int wm   = wid >> 1;     // 0..3 (M)
    const int wn   = wid & 1;      // 0..1 (N)
    const int m0   = blockIdx.y * BM;
    const int n0   = blockIdx.x * BN;

    // ldmatrix lane geometry: row-within-16 and k-half chunk
    const int lm_row = (lane & 7) | (((lane >> 3) & 1) << 3);
    const int lm_hi  = lane >> 4;  // 0: k0-7 chunk, 1: k8-15 chunk

    float acc[2][8][4] = {};

    // ---- stage loader: 4 tensors x 128 rows x 8 chunks(16B) ----
    auto load_stage = [&](int ck) {
        const uint32_t sb = sm0 + (uint32_t)(ck & 1) * STAGE_BYTES;
        const int k0 = ck * BK;
#pragma unroll
        for (int i = 0; i < 4; i++) {
            int lin = tid + i * 256;
            int r = lin >> 3, ch = lin & 7;
            uint32_t sw = (uint32_t)(r * 128) + (uint32_t)((ch ^ (r & 7)) << 4);
            size_t goA = (size_t)(m0 + r) * DMODEL + k0 + ch * 8;
            size_t goB = (size_t)(n0 + r) * DMODEL + k0 + ch * 8;
            CPA(sb + sw,            Ah + goA);
            CPA(sb + A_SZ + sw,     Al + goA);
            CPA(sb + 2 * A_SZ + sw, Wh + goB);
            CPA(sb + 3 * A_SZ + sw, Wl + goB);
        }
    };

    load_stage(0);
    CPA_COMMIT();

    for (int ck = 0; ck < NCHUNK; ck++) {
        if (ck + 1 < NCHUNK) {
            load_stage(ck + 1);
            CPA_COMMIT();
            CPA_WAIT1();
        } else {
            CPA_WAIT0();
        }
        __syncthreads();

        const uint32_t sb = sm0 + (uint32_t)(ck & 1) * STAGE_BYTES;
        const uint32_t aHi = sb, aLo = sb + A_SZ, bHi = sb + 2 * A_SZ, bLo = sb + 3 * A_SZ;

#pragma unroll
        for (int ks = 0; ks < 4; ks++) {
            uint32_t ahf[2][4], alf[2][4];
#pragma unroll
            for (int mt = 0; mt < 2; mt++) {
                int r = wm * 32 + mt * 16 + lm_row;
                uint32_t off = (uint32_t)(r * 128) +
                               (uint32_t)((((ks * 2 + lm_hi) ^ (r & 7))) << 4);
                LDSM4(ahf[mt], aHi + off);
                LDSM4(alf[mt], aLo + off);
            }
            uint32_t bhf[4][4], blf[4][4];
#pragma unroll
            for (int np = 0; np < 4; np++) {
                int n = wn * 64 + np * 16 + lm_row;
                uint32_t off = (uint32_t)(n * 128) +
                               (uint32_t)((((ks * 2 + lm_hi) ^ (n & 7))) << 4);
                LDSM4(bhf[np], bHi + off);
                LDSM4(blf[np], bLo + off);
            }
#pragma unroll
            for (int mt = 0; mt < 2; mt++)
#pragma unroll
                for (int nt = 0; nt < 8; nt++) {
                    int np = nt >> 1, sel = nt & 1;
                    MMA16816(acc[mt][nt], ahf[mt], bhf[np][sel], bhf[np][sel + 2]);
                    MMA16816(acc[mt][nt], alf[mt], bhf[np][sel], bhf[np][sel + 2]);
                    MMA16816(acc[mt][nt], ahf[mt], blf[np][sel], blf[np][sel + 2]);
                }
        }
        __syncthreads();
    }

    // ---- epilogue: bias + store ----
    const int rbase = m0 + wm * 32 + (lane >> 2);
    const int cbase = n0 + wn * 64 + (lane & 3) * 2;
#pragma unroll
    for (int mt = 0; mt < 2; mt++) {
#pragma unroll
        for (int nt = 0; nt < 8; nt++) {
            int col = cbase + nt * 8;
            float2 bv = *(const float2*)(bias + col);
#pragma unroll
            for (int half = 0; half < 2; half++) {
                int t = rbase + mt * 16 + half * 8;
                float2 o;
                o.x = acc[mt][nt][half * 2 + 0] + bv.x;
                o.y = acc[mt][nt][half * 2 + 1] + bv.y;
                if (qkv_mode) {
                    int s_idx = t >> 1, b = t & 1;
                    int h = col >> 6, dk = col & 63;
                    *(float2*)(out + ((size_t)(h * BATCH + b) * SEQ + s_idx) * DKH + dk) = o;
                } else {
                    *(float2*)(out + (size_t)t * DMODEL + col) = o;
                }
            }
        }
    }
}

// ---------------------------------------------------------------------------
// Flash attention, fp32 (proven R1 kernel — mma port next round)
// ---------------------------------------------------------------------------
#define FL_STRIDE 68
#define FLASH_SMEM_FLOATS (4 * 64 * FL_STRIDE + 3 * 64)
#define FLASH_SMEM_BYTES  (FLASH_SMEM_FLOATS * 4)

__global__ __launch_bounds__(256)
void flash_kernel(const float* __restrict__ Q, const float* __restrict__ K,
                  const float* __restrict__ V, float* __restrict__ O)
{
    extern __shared__ float sm[];
    float* Qs   = sm;
    float* Ks   = Qs + 64 * FL_STRIDE;
    float* Vs   = Ks + 64 * FL_STRIDE;
    float* Ss   = Vs + 64 * FL_STRIDE;
    float* mrow = Ss + 64 * FL_STRIDE;
    float* lrow = mrow + 64;
    float* arow = lrow + 64;

    const int qt = blockIdx.x;
    const int hb = blockIdx.y;
    const int tid = threadIdx.x;
    const int tx = tid & 15;
    const int ty = tid >> 4;

    const float* Qb = Q + (size_t)hb * SEQ * DKH + (size_t)qt * 64 * DKH;
    const float* Kb = K + (size_t)hb * SEQ * DKH;
    const float* Vb = V + (size_t)hb * SEQ * DKH;

#pragma unroll
    for (int i = 0; i < 4; i++) {
        int lin = tid + i * 256;
        int r = lin >> 4;
        int dq = lin & 15;
        float4 v = *(const float4*)(Qb + r * DKH + dq * 4);
        Qs[(dq * 4 + 0) * FL_STRIDE + r] = v.x * 0.125f;
        Qs[(dq * 4 + 1) * FL_STRIDE + r] = v.y * 0.125f;
        Qs[(dq * 4 + 2) * FL_STRIDE + r] = v.z * 0.125f;
        Qs[(dq * 4 + 3) * FL_STRIDE + r] = v.w * 0.125f;
    }
    if (tid < 64) { mrow[tid] = -1e30f; lrow[tid] = 0.0f; }

    float o[4][4] = {};

    __syncthreads();

    for (int kt = 0; kt < SEQ / 64; kt++) {
        const float* Kt = Kb + (size_t)kt * 64 * DKH;
        const float* Vt = Vb + (size_t)kt * 64 * DKH;
#pragma unroll
        for (int i = 0; i < 4; i++) {
            int lin = tid + i * 256;
            int r = lin >> 4;
            int dq = lin & 15;
            float4 kv = *(const float4*)(Kt + r * DKH + dq * 4);
            Ks[(dq * 4 + 0) * FL_STRIDE + r] = kv.x;
            Ks[(dq * 4 + 1) * FL_STRIDE + r] = kv.y;
            Ks[(dq * 4 + 2) * FL_STRIDE + r] = kv.z;
            Ks[(dq * 4 + 3) * FL_STRIDE + r] = kv.w;
            float4 vv = *(const float4*)(Vt + r * DKH + dq * 4);
            *(float4*)&Vs[r * FL_STRIDE + dq * 4] = vv;
        }
        __syncthreads();

        float s[4][4] = {};
#pragma unroll 8
        for (int d = 0; d < 64; d++) {
            float4 a4 = *(const float4*)&Qs[d * FL_STRIDE + ty * 4];
            float4 b4 = *(const float4*)&Ks[d * FL_STRIDE + tx * 4];
            float av[4] = {a4.x, a4.y, a4.z, a4.w};
            float bvv[4] = {b4.x, b4.y, b4.z, b4.w};
#pragma unroll
            for (int i = 0; i < 4; i++)
#pragma unroll
                for (int j = 0; j < 4; j++)
                    s[i][j] = fmaf(av[i], bvv[j], s[i][j]);
        }
#pragma unroll
        for (int i = 0; i < 4; i++)
#pragma unroll
            for (int j = 0; j < 4; j++)
                Ss[(ty * 4 + i) * FL_STRIDE + tx * 4 + j] = s[i][j];
        __syncthreads();

        if (tid < 64) {
            float* row = &Ss[tid * FL_STRIDE];
            float mx = mrow[tid];
#pragma unroll 8
            for (int c = 0; c < 64; c++) mx = fmaxf(mx, row[c]);
            float al = __expf(mrow[tid] - mx);
            float sum = 0.0f;
#pragma unroll 8
            for (int c = 0; c < 64; c++) {
                float p = __expf(row[c] - mx);
                row[c] = p;
                sum += p;
            }
            lrow[tid] = lrow[tid] * al + sum;
            mrow[tid] = mx;
            arow[tid] = al;
        }
        __syncthreads();

        float al[4];
#pragma unroll
        for (int i = 0; i < 4; i++) al[i] = arow[ty * 4 + i];
#pragma unroll
        for (int i = 0; i < 4; i++)
#pragma unroll
            for (int j = 0; j < 4; j++)
                o[i][j] *= al[i];

#pragma unroll 8
        for (int c = 0; c < 64; c++) {
            float pv[4];
#pragma unroll
            for (int i = 0; i < 4; i++) pv[i] = Ss[(ty * 4 + i) * FL_STRIDE + c];
            float4 v4 = *(const float4*)&Vs[c * FL_STRIDE + tx * 4];
            float vv[4] = {v4.x, v4.y, v4.z, v4.w};
#pragma unroll
            for (int i = 0; i < 4; i++)
#pragma unroll
                for (int j = 0; j < 4; j++)
                    o[i][j] = fmaf(pv[i], vv[j], o[i][j]);
        }
        __syncthreads();
    }

    const int h = hb / BATCH;
    const int b = hb % BATCH;
#pragma unroll
    for (int i = 0; i < 4; i++) {
        int r = ty * 4 + i;
        float inv = 1.0f / lrow[r];
        int s_idx = qt * 64 + r;
        int t = s_idx * BATCH + b;
        float4 ov;
        ov.x = o[i][0] * inv;
        ov.y = o[i][1] * inv;
        ov.z = o[i][2] * inv;
        ov.w = o[i][3] * inv;
        *(float4*)(O + (size_t)t * DMODEL + h * DKH + tx * 4) = ov;
    }
}

// ---------------------------------------------------------------------------
extern "C" void kernel_launch(void* const* d_in, const int* in_sizes, int n_in,
                              void* d_out, int out_size)
{
    const float* query = (const float*)d_in[0];
    const float* key_  = (const float*)d_in[1];
    const float* value = (const float*)d_in[2];
    const float* Wq = (const float*)d_in[3];
    const float* bq = (const float*)d_in[4];
    const float* Wk = (const float*)d_in[5];
    const float* bk = (const float*)d_in[6];
    const float* Wv = (const float*)d_in[7];
    const float* bv = (const float*)d_in[8];
    const float* Wo = (const float*)d_in[9];
    const float* bo = (const float*)d_in[10];

    float *qp, *kp, *vp, *ap;
    __nv_bfloat16 *Ah, *Al, *Wh, *Wl;
    cudaGetSymbolAddress((void**)&qp, g_q);
    cudaGetSymbolAddress((void**)&kp, g_k);
    cudaGetSymbolAddress((void**)&vp, g_v);
    cudaGetSymbolAddress((void**)&ap, g_attn);
    cudaGetSymbolAddress((void**)&Ah, g_Ah);
    cudaGetSymbolAddress((void**)&Al, g_Al);
    cudaGetSymbolAddress((void**)&Wh, g_Wh);
    cudaGetSymbolAddress((void**)&Wl, g_Wl);

    cudaFuncSetAttribute(flash_kernel,
                         cudaFuncAttributeMaxDynamicSharedMemorySize, FLASH_SMEM_BYTES);
    cudaFuncSetAttribute(gemm_mma_kernel,
                         cudaFuncAttributeMaxDynamicSharedMemorySize, GEMM_SMEM);

    const int nAct4 = TOK * DMODEL / 4;
    const int nW4   = DMODEL * DMODEL / 4;
    dim3 ggrid(DMODEL / BN, TOK / BM);   // (8, 32)

    // Q projection
    cvt_split_kernel<<<nAct4 / 256, 256>>>(query, Ah, Al, nAct4);
    cvt_split_kernel<<<nW4 / 256, 256>>>(Wq, Wh, Wl, nW4);
    gemm_mma_kernel<<<ggrid, 256, GEMM_SMEM>>>(Ah, Al, Wh, Wl, bq, qp, 1);
    // K projection
    cvt_split_kernel<<<nAct4 / 256, 256>>>(key_, Ah, Al, nAct4);
    cvt_split_kernel<<<nW4 / 256, 256>>>(Wk, Wh, Wl, nW4);
    gemm_mma_kernel<<<ggrid, 256, GEMM_SMEM>>>(Ah, Al, Wh, Wl, bk, kp, 1);
    // V projection
    cvt_split_kernel<<<nAct4 / 256, 256>>>(value, Ah, Al, nAct4);
    cvt_split_kernel<<<nW4 / 256, 256>>>(Wv, Wh, Wl, nW4);
    gemm_mma_kernel<<<ggrid, 256, GEMM_SMEM>>>(Ah, Al, Wh, Wl, bv, vp, 1);

    // Attention
    flash_kernel<<<dim3(SEQ / 64, NH * BATCH), 256, FLASH_SMEM_BYTES>>>(qp, kp, vp, ap);

    // Output projection
    cvt_split_kernel<<<nAct4 / 256, 256>>>(ap, Ah, Al, nAct4);
    cvt_split_kernel<<<nW4 / 256, 256>>>(Wo, Wh, Wl, nW4);
    gemm_mma_kernel<<<ggrid, 256, GEMM_SMEM>>>(Ah, Al, Wh, Wl, bo, (float*)d_out, 0);
}

// round 4
// speedup vs baseline: 3.0742x; 2.0836x over previous
#include <cuda_runtime.h>
#include <cuda_bf16.h>
#include <cstdint>

#define SEQ    2048
#define BATCH  2
#define DMODEL 1024
#define NH     16
#define DKH    64
#define TOK    (SEQ * BATCH)   // 4096

// ---------------------------------------------------------------------------
// Scratch (__device__ globals: the sanctioned alloc-free workaround)
// ---------------------------------------------------------------------------
__device__ __nv_bfloat16 g_Ah[TOK * DMODEL];      // split activation hi/lo
__device__ __nv_bfloat16 g_Al[TOK * DMODEL];
__device__ __nv_bfloat16 g_Wh[DMODEL * DMODEL];   // split weight hi/lo
__device__ __nv_bfloat16 g_Wl[DMODEL * DMODEL];

// Q/K/V split bf16, layout [h][b][s][dk]
__device__ __nv_bfloat16 g_Qh[NH * BATCH * SEQ * DKH];
__device__ __nv_bfloat16 g_Ql[NH * BATCH * SEQ * DKH];
__device__ __nv_bfloat16 g_Kh[NH * BATCH * SEQ * DKH];
__device__ __nv_bfloat16 g_Kl[NH * BATCH * SEQ * DKH];
__device__ __nv_bfloat16 g_Vh[NH * BATCH * SEQ * DKH];
__device__ __nv_bfloat16 g_Vl[NH * BATCH * SEQ * DKH];

// ---------------------------------------------------------------------------
// Helpers (sm_80-era PTX only: tcgen05 is blocked by the compute_103 target)
// ---------------------------------------------------------------------------
__device__ __forceinline__ uint32_t smem_u32(const void* p) {
    uint32_t a;
    asm("{ .reg .u64 t; cvta.to.shared.u64 t, %1; cvt.u32.u64 %0, t; }"
        : "=r"(a) : "l"(p));
    return a;
}

#define CPA(dst, src) \
    asm volatile("cp.async.cg.shared.global [%0], [%1], 16;" :: "r"(dst), "l"(src))
#define CPA_COMMIT() asm volatile("cp.async.commit_group;" ::: "memory")
#define CPA_WAIT0()  asm volatile("cp.async.wait_group 0;" ::: "memory")
#define CPA_WAIT1()  asm volatile("cp.async.wait_group 1;" ::: "memory")

#define LDSM4(r, addr) \
    asm volatile("ldmatrix.sync.aligned.m8n8.x4.shared.b16 {%0,%1,%2,%3}, [%4];" \
        : "=r"((r)[0]), "=r"((r)[1]), "=r"((r)[2]), "=r"((r)[3]) : "r"(addr))

#define LDSM4T(r, addr) \
    asm volatile("ldmatrix.sync.aligned.m8n8.x4.trans.shared.b16 {%0,%1,%2,%3}, [%4];" \
        : "=r"((r)[0]), "=r"((r)[1]), "=r"((r)[2]), "=r"((r)[3]) : "r"(addr))

#define MMA16816(c, a, b0, b1) \
    asm volatile("mma.sync.aligned.m16n8k16.row.col.f32.bf16.bf16.f32 " \
        "{%0,%1,%2,%3}, {%4,%5,%6,%7}, {%8,%9}, {%0,%1,%2,%3};" \
        : "+f"((c)[0]), "+f"((c)[1]), "+f"((c)[2]), "+f"((c)[3]) \
        : "r"((a)[0]), "r"((a)[1]), "r"((a)[2]), "r"((a)[3]), "r"(b0), "r"(b1))

// split a float pair into bf16-hi and bf16-lo packed words (lo value in low half)
__device__ __forceinline__ void pack_hilo(float lo, float hi, uint32_t& h, uint32_t& l) {
    __nv_bfloat162 h2 = __float22bfloat162_rn(make_float2(lo, hi));
    float2 hf = __bfloat1622float2(h2);
    __nv_bfloat162 l2 = __float22bfloat162_rn(make_float2(lo - hf.x, hi - hf.y));
    h = *(uint32_t*)&h2;
    l = *(uint32_t*)&l2;
}

// ---------------------------------------------------------------------------
// fp32 -> bf16 hi/lo split (pre-pass)
// ---------------------------------------------------------------------------
__global__ __launch_bounds__(256)
void cvt_split_kernel(const float* __restrict__ x, __nv_bfloat16* __restrict__ hi,
                      __nv_bfloat16* __restrict__ lo, int n4)
{
    int i = blockIdx.x * blockDim.x + threadIdx.x;
    if (i >= n4) return;
    float4 v = ((const float4*)x)[i];
    uint32_t h0, l0, h1, l1;
    pack_hilo(v.x, v.y, h0, l0);
    pack_hilo(v.z, v.w, h1, l1);
    ((uint2*)hi)[i] = make_uint2(h0, h1);
    ((uint2*)lo)[i] = make_uint2(l0, l1);
}

// ---------------------------------------------------------------------------
// bf16x3 tensor-core GEMM via mma.sync:
//   out[t][n] = (sum_k A[t][k]*W[n][k] + bias[n]) * scale
// qkv_mode=1: split-bf16 scatter to [h][b][s][dk] (outh/outl)
// qkv_mode=0: fp32 [t][n] to outf
// ---------------------------------------------------------------------------
#define BM 128
#define BN 128
#define BK 64
#define A_SZ (BM * BK * 2)                 // 16384 bytes per half-tensor
#define STAGE_BYTES (4 * A_SZ)             // Ah, Al, Bh, Bl = 65536
#define GEMM_SMEM (2 * STAGE_BYTES + 1024)
#define NCHUNK (DMODEL / BK)               // 16

__global__ __launch_bounds__(256, 1)
void gemm_mma_kernel(const __nv_bfloat16* __restrict__ Ah, const __nv_bfloat16* __restrict__ Al,
                     const __nv_bfloat16* __restrict__ Wh, const __nv_bfloat16* __restrict__ Wl,
                     const float* __restrict__ bias,
                     __nv_bfloat16* __restrict__ outh, __nv_bfloat16* __restrict__ outl,
                     float* __restrict__ outf, int qkv_mode, float scale)
{
    extern __shared__ char dsm_raw[];
    char* dsm = (char*)(((uintptr_t)dsm_raw + 1023) & ~(uintptr_t)1023);
    const uint32_t sm0 = smem_u32(dsm);

    const int tid  = threadIdx.x;
    const int wid  = tid >> 5;
    const int lane = tid & 31;
    const int wm   = wid >> 1;     // 0..3 (M)
    const int wn   = wid & 1;      // 0..1 (N)
    const int m0   = blockIdx.y * BM;
    const int n0   = blockIdx.x * BN;

    const int lm_row = (lane & 7) | (((lane >> 3) & 1) << 3);
    const int lm_hi  = lane >> 4;

    float acc[2][8][4] = {};

    auto load_stage = [&](int ck) {
        const uint32_t sb = sm0 + (uint32_t)(ck & 1) * STAGE_BYTES;
        const int k0 = ck * BK;
#pragma unroll
        for (int i = 0; i < 4; i++) {
            int lin = tid + i * 256;
            int r = lin >> 3, ch = lin & 7;
            uint32_t sw = (uint32_t)(r * 128) + (uint32_t)((ch ^ (r & 7)) << 4);
            size_t goA = (size_t)(m0 + r) * DMODEL + k0 + ch * 8;
            size_t goB = (size_t)(n0 + r) * DMODEL + k0 + ch * 8;
            CPA(sb + sw,            Ah + goA);
            CPA(sb + A_SZ + sw,     Al + goA);
            CPA(sb + 2 * A_SZ + sw, Wh + goB);
            CPA(sb + 3 * A_SZ + sw, Wl + goB);
        }
    };

    load_stage(0);
    CPA_COMMIT();

    for (int ck = 0; ck < NCHUNK; ck++) {
        if (ck + 1 < NCHUNK) {
            load_stage(ck + 1);
            CPA_COMMIT();
            CPA_WAIT1();
        } else {
            CPA_WAIT0();
        }
        __syncthreads();

        const uint32_t sb = sm0 + (uint32_t)(ck & 1) * STAGE_BYTES;
        const uint32_t aHi = sb, aLo = sb + A_SZ, bHi = sb + 2 * A_SZ, bLo = sb + 3 * A_SZ;

#pragma unroll
        for (int ks = 0; ks < 4; ks++) {
            uint32_t ahf[2][4], alf[2][4];
#pragma unroll
            for (int mt = 0; mt < 2; mt++) {
                int r = wm * 32 + mt * 16 + lm_row;
                uint32_t off = (uint32_t)(r * 128) +
                               (uint32_t)((((ks * 2 + lm_hi) ^ (r & 7))) << 4);
                LDSM4(ahf[mt], aHi + off);
                LDSM4(alf[mt], aLo + off);
            }
            uint32_t bhf[4][4], blf[4][4];
#pragma unroll
            for (int np = 0; np < 4; np++) {
                int n = wn * 64 + np * 16 + lm_row;
                uint32_t off = (uint32_t)(n * 128) +
                               (uint32_t)((((ks * 2 + lm_hi) ^ (n & 7))) << 4);
                LDSM4(bhf[np], bHi + off);
                LDSM4(blf[np], bLo + off);
            }
#pragma unroll
            for (int mt = 0; mt < 2; mt++)
#pragma unroll
                for (int nt = 0; nt < 8; nt++) {
                    int np = nt >> 1, sel = nt & 1;
                    MMA16816(acc[mt][nt], ahf[mt], bhf[np][sel], bhf[np][sel + 2]);
                    MMA16816(acc[mt][nt], alf[mt], bhf[np][sel], bhf[np][sel + 2]);
                    MMA16816(acc[mt][nt], ahf[mt], blf[np][sel], blf[np][sel + 2]);
                }
        }
        __syncthreads();
    }

    // ---- epilogue ----
    const int rbase = m0 + wm * 32 + (lane >> 2);
    const int cbase = n0 + wn * 64 + (lane & 3) * 2;
#pragma unroll
    for (int mt = 0; mt < 2; mt++) {
#pragma unroll
        for (int nt = 0; nt < 8; nt++) {
            int col = cbase + nt * 8;
            float2 bv = *(const float2*)(bias + col);
#pragma unroll
            for (int half = 0; half < 2; half++) {
                int t = rbase + mt * 16 + half * 8;
                float ox = (acc[mt][nt][half * 2 + 0] + bv.x) * scale;
                float oy = (acc[mt][nt][half * 2 + 1] + bv.y) * scale;
                if (qkv_mode) {
                    int s_idx = t >> 1, b = t & 1;
                    int h = col >> 6, dk = col & 63;
                    size_t off = ((size_t)(h * BATCH + b) * SEQ + s_idx) * DKH + dk;
                    uint32_t ph, pl;
                    pack_hilo(ox, oy, ph, pl);
                    *(uint32_t*)(outh + off) = ph;
                    *(uint32_t*)(outl + off) = pl;
                } else {
                    *(float2*)(outf + (size_t)t * DMODEL + col) = make_float2(ox, oy);
                }
            }
        }
    }
}

// ---------------------------------------------------------------------------
// Flash attention on mma.sync, split bf16 in and out.
// CTA: 128 q-rows x one (h,b). 8 warps: wm=wid>>1 (32 q-rows), wn=wid&1
// (key half). Warp-local online softmax over its key subset; split-k merge
// across wn pairs in the epilogue. Output written as split bf16 [t][dmodel].
// ---------------------------------------------------------------------------
#define FQ_SZ   (128 * 64 * 2)             // 16384 bytes (one Q half-tensor)
#define KV_T_SZ (128 * 64 * 2)             // 16384 per tensor per chunk
#define KV_STAGE (4 * KV_T_SZ)             // Kh,Kl,Vh,Vl = 65536
#define FL_KV_OFF (2 * FQ_SZ)              // 32768
#define FLASH_SMEM (FL_KV_OFF + 2 * KV_STAGE + 1024)   // ~161 KB
#define NKC (SEQ / 128)                    // 16

__global__ __launch_bounds__(256, 1)
void flash_mma_kernel(const __nv_bfloat16* __restrict__ Qh, const __nv_bfloat16* __restrict__ Ql,
                      const __nv_bfloat16* __restrict__ Kh, const __nv_bfloat16* __restrict__ Kl,
                      const __nv_bfloat16* __restrict__ Vh, const __nv_bfloat16* __restrict__ Vl,
                      __nv_bfloat16* __restrict__ Oh, __nv_bfloat16* __restrict__ Ol)
{
    extern __shared__ char dsm_raw[];
    char* dsm = (char*)(((uintptr_t)dsm_raw + 1023) & ~(uintptr_t)1023);
    const uint32_t sm0 = smem_u32(dsm);
    const uint32_t sQh = sm0, sQl = sm0 + FQ_SZ;

    const int qt  = blockIdx.x;
    const int hb  = blockIdx.y;            // h*BATCH + b
    const int tid = threadIdx.x;
    const int wid = tid >> 5;
    const int lane = tid & 31;
    const int wm  = wid >> 1;
    const int wn  = wid & 1;

    const int lm_row = (lane & 7) | (((lane >> 3) & 1) << 3);
    const int lm_hi  = lane >> 4;

    const size_t hb_base = (size_t)hb * SEQ * DKH;

    // ---- load Q tile (persistent) + KV chunk 0 ----
    {
        size_t qbase = hb_base + (size_t)qt * 128 * DKH;
#pragma unroll
        for (int i = 0; i < 4; i++) {
            int lin = tid + i * 256;
            int r = lin >> 3, ch = lin & 7;
            uint32_t sw = (uint32_t)(r * 128) + (uint32_t)((ch ^ (r & 7)) << 4);
            size_t go = qbase + (size_t)r * DKH + ch * 8;
            CPA(sQh + sw, Qh + go);
            CPA(sQl + sw, Ql + go);
        }
    }
    auto load_kv = [&](int kc) {
        const uint32_t sb = sm0 + FL_KV_OFF + (uint32_t)(kc & 1) * KV_STAGE;
        size_t gbase = hb_base + (size_t)kc * 128 * DKH;
#pragma unroll
        for (int i = 0; i < 4; i++) {
            int lin = tid + i * 256;
            int r = lin >> 3, ch = lin & 7;
            uint32_t sw = (uint32_t)(r * 128) + (uint32_t)((ch ^ (r & 7)) << 4);
            size_t go = gbase + (size_t)r * DKH + ch * 8;
            CPA(sb + sw,               Kh + go);
            CPA(sb + KV_T_SZ + sw,     Kl + go);
            CPA(sb + 2 * KV_T_SZ + sw, Vh + go);
            CPA(sb + 3 * KV_T_SZ + sw, Vl + go);
        }
    };
    load_kv(0);
    CPA_COMMIT();

    float m[4] = {-1e30f, -1e30f, -1e30f, -1e30f};
    float l[4] = {0.f, 0.f, 0.f, 0.f};
    float acc_o[2][8][4] = {};

    for (int kc = 0; kc < NKC; kc++) {
        if (kc + 1 < NKC) {
            load_kv(kc + 1);
            CPA_COMMIT();
            CPA_WAIT1();
        } else {
            CPA_WAIT0();
        }
        __syncthreads();

        const uint32_t sb = sm0 + FL_KV_OFF + (uint32_t)(kc & 1) * KV_STAGE;
        const uint32_t sKh = sb, sKl = sb + KV_T_SZ;
        const uint32_t sVh = sb + 2 * KV_T_SZ, sVl = sb + 3 * KV_T_SZ;

        // ---- S = Q K^T  (Q pre-scaled by 1/8 at projection time) ----
        float accs[2][8][4] = {};
#pragma unroll
        for (int ks = 0; ks < 4; ks++) {
            uint32_t ahf[2][4], alf[2][4];
#pragma unroll
            for (int mt = 0; mt < 2; mt++) {
                int r = wm * 32 + mt * 16 + lm_row;
                uint32_t off = (uint32_t)(r * 128) +
                               (uint32_t)((((ks * 2 + lm_hi) ^ (r & 7))) << 4);
                LDSM4(ahf[mt], sQh + off);
                LDSM4(alf[mt], sQl + off);
            }
            uint32_t bhf[4][4], blf[4][4];
#pragma unroll
            for (int np = 0; np < 4; np++) {
                int n = wn * 64 + np * 16 + lm_row;
                uint32_t off = (uint32_t)(n * 128) +
                               (uint32_t)((((ks * 2 + lm_hi) ^ (n & 7))) << 4);
                LDSM4(bhf[np], sKh + off);
                LDSM4(blf[np], sKl + off);
            }
#pragma unroll
            for (int mt = 0; mt < 2; mt++)
#pragma unroll
                for (int nt = 0; nt < 8; nt++) {
                    int np = nt >> 1, sel = nt & 1;
                    MMA16816(accs[mt][nt], ahf[mt], bhf[np][sel], bhf[np][sel + 2]);
                    MMA16816(accs[mt][nt], alf[mt], bhf[np][sel], bhf[np][sel + 2]);
                    MMA16816(accs[mt][nt], ahf[mt], blf[np][sel], blf[np][sel + 2]);
                }
        }

        // ---- warp-local online softmax (keys of this wn only) ----
#pragma unroll
        for (int mt = 0; mt < 2; mt++) {
#pragma unroll
            for (int half = 0; half < 2; half++) {
                const int rs = mt * 2 + half;
                float mx = -1e30f;
#pragma unroll
                for (int nt = 0; nt < 8; nt++) {
                    mx = fmaxf(mx, accs[mt][nt][half * 2 + 0]);
                    mx = fmaxf(mx, accs[mt][nt][half * 2 + 1]);
                }
                mx = fmaxf(mx, __shfl_xor_sync(0xffffffffu, mx, 1));
                mx = fmaxf(mx, __shfl_xor_sync(0xffffffffu, mx, 2));
                float mn = fmaxf(m[rs], mx);
                float alpha = __expf(m[rs] - mn);
                m[rs] = mn;
                float sum = 0.f;
#pragma unroll
                for (int nt = 0; nt < 8; nt++) {
#pragma unroll
                    for (int j = 0; j < 2; j++) {
                        float p = __expf(accs[mt][nt][half * 2 + j] - mn);
                        accs[mt][nt][half * 2 + j] = p;
                        sum += p;
                    }
                }
                sum += __shfl_xor_sync(0xffffffffu, sum, 1);
                sum += __shfl_xor_sync(0xffffffffu, sum, 2);
                l[rs] = l[rs] * alpha + sum;
#pragma unroll
                for (int nt = 0; nt < 8; nt++) {
                    acc_o[mt][nt][half * 2 + 0] *= alpha;
                    acc_o[mt][nt][half * 2 + 1] *= alpha;
                }
            }
        }

        // ---- O += P V  (P from registers, V via ldmatrix.trans) ----
#pragma unroll
        for (int j = 0; j < 4; j++) {          // key16 step within warp's 64 keys
            uint32_t vhf[4][4], vlf[4][4];
            const int kk = wn * 64 + j * 16 + ((lane >> 3) & 1) * 8 + (lane & 7);
            const int nb = (lane >> 4) * 8;
#pragma unroll
            for (int np = 0; np < 4; np++) {
                int n = np * 16 + nb;
                uint32_t off = (uint32_t)(kk * 128) +
                               (uint32_t)((((n >> 3) ^ (kk & 7))) << 4);
                LDSM4T(vhf[np], sVh + off);
                LDSM4T(vlf[np], sVl + off);
            }
#pragma unroll
            for (int mt = 0; mt < 2; mt++) {
                uint32_t ah[4], ap[4];
                pack_hilo(accs[mt][2 * j][0],     accs[mt][2 * j][1],     ah[0], ap[0]);
                pack_hilo(accs[mt][2 * j][2],     accs[mt][2 * j][3],     ah[1], ap[1]);
                pack_hilo(accs[mt][2 * j + 1][0], accs[mt][2 * j + 1][1], ah[2], ap[2]);
                pack_hilo(accs[mt][2 * j + 1][2], accs[mt][2 * j + 1][3], ah[3], ap[3]);
#pragma unroll
                for (int nto = 0; nto < 8; nto++) {
                    int np = nto >> 1, s2 = (nto & 1) * 2;
                    MMA16816(acc_o[mt][nto], ah, vhf[np][s2], vhf[np][s2 + 1]);
                    MMA16816(acc_o[mt][nto], ap, vhf[np][s2], vhf[np][s2 + 1]);
                    MMA16816(acc_o[mt][nto], ah, vlf[np][s2], vlf[np][s2 + 1]);
                }
            }
        }
        __syncthreads();
    }

    // ---- merge wn pairs + store split bf16 ----
    float* bufO  = (float*)(dsm + FL_KV_OFF);                       // [4][32][66]
    float2* bufML = (float2*)(dsm + FL_KV_OFF + 4 * 32 * 66 * 4);   // [4][32]

    if (wn == 1) {
        float* mybuf = bufO + wm * 32 * 66;
#pragma unroll
        for (int mt = 0; mt < 2; mt++)
#pragma unroll
            for (int half = 0; half < 2; half++) {
                int row = mt * 16 + half * 8 + (lane >> 2);
#pragma unroll
                for (int nt = 0; nt < 8; nt++) {
                    int c0 = nt * 8 + (lane & 3) * 2;
                    mybuf[row * 66 + c0]     = acc_o[mt][nt][half * 2 + 0];
                    mybuf[row * 66 + c0 + 1] = acc_o[mt][nt][half * 2 + 1];
                }
                if ((lane & 3) == 0)
                    bufML[wm * 32 + row] = make_float2(m[mt * 2 + half], l[mt * 2 + half]);
            }
    }
    __syncthreads();

    if (wn == 0) {
        const int h = hb / BATCH;
        const int b = hb % BATCH;
        const float* mybuf = bufO + wm * 32 * 66;
#pragma unroll
        for (int mt = 0; mt < 2; mt++)
#pragma unroll
            for (int half = 0; half < 2; half++) {
                const int rs = mt * 2 + half;
                int row = mt * 16 + half * 8 + (lane >> 2);
                float2 ml1 = bufML[wm * 32 + row];
                float mm = fmaxf(m[rs], ml1.x);
                float e0 = __expf(m[rs] - mm);
                float e1 = __expf(ml1.x - mm);
                float inv = 1.0f / (e0 * l[rs] + e1 * ml1.y);
                int s_global = qt * 128 + wm * 32 + row;
                size_t rowoff = (size_t)(s_global * BATCH + b) * DMODEL + h * DKH;
#pragma unroll
                for (int nt = 0; nt < 8; nt++) {
                    int c0 = nt * 8 + (lane & 3) * 2;
                    float ox = (e0 * acc_o[mt][nt][half * 2 + 0] + e1 * mybuf[row * 66 + c0]) * inv;
                    float oy = (e0 * acc_o[mt][nt][half * 2 + 1] + e1 * mybuf[row * 66 + c0 + 1]) * inv;
                    uint32_t ph, pl;
                    pack_hilo(ox, oy, ph, pl);
                    *(uint32_t*)(Oh + rowoff + c0) = ph;
                    *(uint32_t*)(Ol + rowoff + c0) = pl;
                }
            }
    }
}

// ---------------------------------------------------------------------------
extern "C" void kernel_launch(void* const* d_in, const int* in_sizes, int n_in,
                              void* d_out, int out_size)
{
    const float* query = (const float*)d_in[0];
    const float* key_  = (const float*)d_in[1];
    const float* value = (const float*)d_in[2];
    const float* Wq = (const float*)d_in[3];
    const float* bq = (const float*)d_in[4];
    const float* Wk = (const float*)d_in[5];
    const float* bk = (const float*)d_in[6];
    const float* Wv = (const float*)d_in[7];
    const float* bv = (const float*)d_in[8];
    const float* Wo = (const float*)d_in[9];
    const float* bo = (const float*)d_in[10];

    __nv_bfloat16 *Ah, *Al, *Wh, *Wl, *Qh, *Ql, *Kh, *Kl, *Vh, *Vl;
    cudaGetSymbolAddress((void**)&Ah, g_Ah);
    cudaGetSymbolAddress((void**)&Al, g_Al);
    cudaGetSymbolAddress((void**)&Wh, g_Wh);
    cudaGetSymbolAddress((void**)&Wl, g_Wl);
    cudaGetSymbolAddress((void**)&Qh, g_Qh);
    cudaGetSymbolAddress((void**)&Ql, g_Ql);
    cudaGetSymbolAddress((void**)&Kh, g_Kh);
    cudaGetSymbolAddress((void**)&Kl, g_Kl);
    cudaGetSymbolAddress((void**)&Vh, g_Vh);
    cudaGetSymbolAddress((void**)&Vl, g_Vl);

    cudaFuncSetAttribute(gemm_mma_kernel,
                         cudaFuncAttributeMaxDynamicSharedMemorySize, GEMM_SMEM);
    cudaFuncSetAttribute(flash_mma_kernel,
                         cudaFuncAttributeMaxDynamicSharedMemorySize, FLASH_SMEM);

    const int nAct4 = TOK * DMODEL / 4;
    const int nW4   = DMODEL * DMODEL / 4;
    dim3 ggrid(DMODEL / BN, TOK / BM);   // (8, 32)

    // Q projection (pre-scaled by 1/sqrt(dk) = 0.125)
    cvt_split_kernel<<<nAct4 / 256, 256>>>(query, Ah, Al, nAct4);
    cvt_split_kernel<<<nW4 / 256, 256>>>(Wq, Wh, Wl, nW4);
    gemm_mma_kernel<<<ggrid, 256, GEMM_SMEM>>>(Ah, Al, Wh, Wl, bq, Qh, Ql, nullptr, 1, 0.125f);
    // K projection
    cvt_split_kernel<<<nAct4 / 256, 256>>>(key_, Ah, Al, nAct4);
    cvt_split_kernel<<<nW4 / 256, 256>>>(Wk, Wh, Wl, nW4);
    gemm_mma_kernel<<<ggrid, 256, GEMM_SMEM>>>(Ah, Al, Wh, Wl, bk, Kh, Kl, nullptr, 1, 1.0f);
    // V projection
    cvt_split_kernel<<<nAct4 / 256, 256>>>(value, Ah, Al, nAct4);
    cvt_split_kernel<<<nW4 / 256, 256>>>(Wv, Wh, Wl, nW4);
    gemm_mma_kernel<<<ggrid, 256, GEMM_SMEM>>>(Ah, Al, Wh, Wl, bv, Vh, Vl, nullptr, 1, 1.0f);

    // Attention (writes split bf16 attn output into Ah/Al)
    flash_mma_kernel<<<dim3(SEQ / 128, NH * BATCH), 256, FLASH_SMEM>>>(
        Qh, Ql, Kh, Kl, Vh, Vl, Ah, Al);

    // Output projection
    cvt_split_kernel<<<nW4 / 256, 256>>>(Wo, Wh, Wl, nW4);
    gemm_mma_kernel<<<ggrid, 256, GEMM_SMEM>>>(Ah, Al, Wh, Wl, bo, nullptr, nullptr,
                                               (float*)d_out, 0, 1.0f);
}